// round 3
// baseline (speedup 1.0000x reference)
#include <cuda_runtime.h>
#include <math.h>

// ---------------- problem constants ----------------
#define IMG   256
#define PP    49           // patch pixels (7x7)
#define WN    37           // search window
#define NOFF  (WN*WN)      // 1369
#define INC   18           // WN/2
#define RPAD  21           // PATCH/2 + WN/2
#define HP    298          // IMG + 2*RPAD
#define PG    292          // patch-grid size = IMG + WN - 1
#define LTOT  (PG*PG)      // 85264
#define NC    4096         // total centers (64x64)
#define M1    18
#define M2    55
#define CENTER_OFF (INC*WN + INC)   // 684
#define PPAD  56           // padded patch stride (14 float4 chunks)
#define NCH4  14           // PPAD/4

// ---------------- device scratch ----------------
__device__ float g_pad_y[HP*HP];
__device__ float g_pad_x[HP*HP];
__device__ float g_den1[IMG*IMG];
__device__ int   g_idx1[NC*M1];
__device__ int   g_idx2[NC*M2];
__device__ float g_xsum[PP*LTOT];
__device__ float g_wsum[LTOT];

// ---------------- reflect pad 256 -> 298 ----------------
__global__ void pad_input_kernel(const float* __restrict__ src, int use_den1) {
    int t = blockIdx.x * blockDim.x + threadIdx.x;
    if (t >= HP*HP) return;
    int y = t / HP - RPAD, x = t % HP - RPAD;
    y = (y < 0) ? -y : ((y > IMG-1) ? 2*(IMG-1) - y : y);
    x = (x < 0) ? -x : ((x > IMG-1) ? 2*(IMG-1) - x : x);
    float v = use_den1 ? g_den1[y*IMG + x] : src[y*IMG + x];
    if (use_den1) g_pad_x[t] = v; else g_pad_y[t] = v;
}

// ---------------- zero accumulators ----------------
__global__ void zero_kernel() {
    const int total = (PP+1)*LTOT;
    for (int t = blockIdx.x*blockDim.x + threadIdx.x; t < total; t += gridDim.x*blockDim.x) {
        if (t < PP*LTOT) g_xsum[t] = 0.f; else g_wsum[t - PP*LTOT] = 0.f;
    }
}

// ---------------- block matching via exact radix select ----------------
// key = (ordered_dist_bits << 16) | offset_index  -> unique 48-bit keys.
// 4-column tiling: 70 window loads serve 4 offsets (196 before).
template<int M, bool USE_X>
__global__ __launch_bounds__(256) void bm_kernel() {
    __shared__ float win[43*43 + 16];   // +pad: col-tile reads overrun by <=3
    __shared__ unsigned int hist[256];
    __shared__ unsigned int wsum[8];
    __shared__ unsigned int s_selbin, s_need, s_cnt;

    const float* pad = USE_X ? g_pad_x : g_pad_y;
    int* idx_out = (M == M1) ? g_idx1 : g_idx2;

    const int tid = threadIdx.x;
    const int ci = blockIdx.x >> 6, cj = blockIdx.x & 63;
    const int r0 = 4*ci, c0 = 4*cj;

    for (int t = tid; t < 43*43; t += 256)
        win[t] = pad[(r0 + t/43)*HP + (c0 + t%43)];
    __syncthreads();

    float cp[PP];
#pragma unroll
    for (int d = 0; d < PP; ++d) cp[d] = win[(INC + d/7)*43 + (INC + d%7)];

    unsigned long long key[8];
#pragma unroll
    for (int q = 0; q < 8; ++q) key[q] = ~0ull;

    // tiles: 37 rows x 10 col-groups of 4 (last group has 1 valid col)
#pragma unroll
    for (int rq = 0; rq < 2; ++rq) {
        int tile = tid + 256*rq;
        if (tile < 370) {
            int o0 = tile / 10, c4 = (tile % 10) * 4;
            float s0=0.f, s1=0.f, s2=0.f, s3=0.f;
#pragma unroll
            for (int di = 0; di < 7; ++di) {
                float w[10];
                const float* wr = &win[(o0+di)*43 + c4];
#pragma unroll
                for (int x = 0; x < 10; ++x) w[x] = wr[x];
#pragma unroll
                for (int dj = 0; dj < 7; ++dj) {
                    float cv = cp[di*7+dj];
                    float d0 = w[dj]   - cv; s0 = fmaf(d0,d0,s0);
                    float d1 = w[dj+1] - cv; s1 = fmaf(d1,d1,s1);
                    float d2 = w[dj+2] - cv; s2 = fmaf(d2,d2,s2);
                    float d3 = w[dj+3] - cv; s3 = fmaf(d3,d3,s3);
                }
            }
            float sv[4] = {s0,s1,s2,s3};
#pragma unroll
            for (int cc = 0; cc < 4; ++cc) {
                int o1 = c4 + cc;
                if (o1 < WN) {
                    int t = o0*WN + o1;
                    unsigned int u = __float_as_uint(sv[cc]) | 0x80000000u;
                    if (t == CENTER_OFF) u = 0u;
                    key[rq*4+cc] = ((unsigned long long)u << 16) | (unsigned int)t;
                }
            }
        }
    }

    // 6-pass MSB radix select for the M-th smallest key
    unsigned long long prefix = 0ull;
    unsigned int need = M;
#pragma unroll 1
    for (int pass = 0; pass < 6; ++pass) {
        int shift = 40 - 8*pass;
        hist[tid] = 0;
        __syncthreads();
#pragma unroll
        for (int q = 0; q < 8; ++q) {
            if (key[q] != ~0ull && (key[q] >> (shift + 8)) == prefix)
                atomicAdd(&hist[(unsigned int)(key[q] >> shift) & 255u], 1u);
        }
        __syncthreads();
        unsigned int h = hist[tid];
        unsigned int v = h;
#pragma unroll
        for (int o = 1; o < 32; o <<= 1) {
            unsigned int n = __shfl_up_sync(0xffffffffu, v, o);
            if ((tid & 31) >= o) v += n;
        }
        if ((tid & 31) == 31) wsum[tid >> 5] = v;
        __syncthreads();
        if (tid < 8) {
            unsigned int w = wsum[tid];
            unsigned int x = w;
#pragma unroll
            for (int o = 1; o < 8; o <<= 1) {
                unsigned int n = __shfl_up_sync(0xffu, x, o);
                if (tid >= o) x += n;
            }
            wsum[tid] = x - w;   // exclusive
        }
        __syncthreads();
        unsigned int excl = v - h + wsum[tid >> 5];
        if (excl < need && need <= excl + h) {
            s_selbin = (unsigned int)tid;
            s_need   = need - excl;
        }
        __syncthreads();
        prefix = (prefix << 8) | (unsigned long long)s_selbin;
        need = s_need;
    }
    if (tid == 0) s_cnt = 0;
    __syncthreads();
#pragma unroll
    for (int q = 0; q < 8; ++q) {
        if (key[q] <= prefix) {
            unsigned int pos = atomicAdd(&s_cnt, 1u);
            int t = (int)(key[q] & 0xffffu);
            idx_out[blockIdx.x*M + pos] = (r0 + t/WN)*PG + (c0 + t%WN);
        }
    }
}

// ---------------- batched denoise: one block per group ----------------
// A = G G^T (+cI) symmetric.  Register-row sweep => a = -A^{-1}.
// theta = I + c*a (symmetric). Xh = theta*Y. wts_k = 1/||theta_k||^2.
template<int M, int S, int AROWS, int KT, bool ADDC, bool GUIDE_X, bool RELOAD, int NT>
__global__ __launch_bounds__(NT) void denoise_kernel(const float* __restrict__ sigma_p) {
    __shared__ __align__(16) float Gs[AROWS*PPAD];
    __shared__ __align__(16) float A [AROWS*S];
    __shared__ __align__(16) float rowk[S];
    __shared__ float wrow[M];
    __shared__ int   fidx[M];

    const int tid = threadIdx.x;
    const int b   = blockIdx.x;
    const int* idx = (M == M1) ? g_idx1 : g_idx2;
    const float* gpad = GUIDE_X ? g_pad_x : g_pad_y;
    const float sg = *sigma_p;
    const float c  = (float)PP * sg * sg;
    constexpr bool SWP = (M <= 32);   // sweep confined to warp 0

    if (tid < M) fidx[tid] = idx[b*M + tid];
    if (M == M1) {   // zero pad columns of A (M2 grid covers everything)
        for (int t = tid; t < AROWS*S; t += NT) A[t] = 0.f;
    }
    __syncthreads();

    // gather guide patches (rows >= M and cols >= PP zero-padded)
    for (int t = tid; t < AROWS*PPAD; t += NT) {
        int k = t / PPAD, col = t % PPAD;
        float v = 0.f;
        if (col < PP && k < M) {
            int f = fidx[k]; int r = f / PG, cc = f % PG;
            v = gpad[(r + col/7)*HP + (cc + col%7)];
        }
        Gs[t] = v;
    }
    __syncthreads();

    // ---- Gram ----
    if (M == M1) {
        // 1x1 over triangle (171 items)
        const int T = M*(M+1)/2;
        for (int t = tid; t < T; t += NT) {
            int a0 = (int)((sqrtf(8.0f*(float)t + 1.0f) - 1.0f)*0.5f);
            while ((a0+1)*(a0+2)/2 <= t) ++a0;
            while (a0*(a0+1)/2 > t) --a0;
            int b0 = t - a0*(a0+1)/2;
            const float4* ra = (const float4*)(Gs + a0*PPAD);
            const float4* rb = (const float4*)(Gs + b0*PPAD);
            float s = 0.f;
#pragma unroll
            for (int g = 0; g < NCH4; ++g) {
                float4 x = ra[g], y = rb[g];
                s = fmaf(x.x,y.x,s); s = fmaf(x.y,y.y,s);
                s = fmaf(x.z,y.z,s); s = fmaf(x.w,y.w,s);
            }
            if (ADDC && a0 == b0) s += c;
            A[a0*S + b0] = s;
            A[b0*S + a0] = s;
        }
    } else {
        // 4x4 register tiles over 14x14 triangle tile grid (105 tiles)
        if (tid < 105) {
            int ti = (int)((sqrtf(8.0f*(float)tid + 1.0f) - 1.0f)*0.5f);
            while ((ti+1)*(ti+2)/2 <= tid) ++ti;
            while (ti*(ti+1)/2 > tid) --ti;
            int tj = tid - ti*(ti+1)/2;
            int i0 = 4*ti, j0 = 4*tj;
            float acc[4][4];
#pragma unroll
            for (int r = 0; r < 4; ++r)
#pragma unroll
                for (int q = 0; q < 4; ++q) acc[r][q] = 0.f;
#pragma unroll
            for (int g = 0; g < NCH4; ++g) {
                float4 av[4], bv[4];
#pragma unroll
                for (int r = 0; r < 4; ++r) {
                    av[r] = ((const float4*)(Gs + (i0+r)*PPAD))[g];
                    bv[r] = ((const float4*)(Gs + (j0+r)*PPAD))[g];
                }
#pragma unroll
                for (int r = 0; r < 4; ++r)
#pragma unroll
                    for (int q = 0; q < 4; ++q) {
                        acc[r][q] = fmaf(av[r].x, bv[q].x, acc[r][q]);
                        acc[r][q] = fmaf(av[r].y, bv[q].y, acc[r][q]);
                        acc[r][q] = fmaf(av[r].z, bv[q].z, acc[r][q]);
                        acc[r][q] = fmaf(av[r].w, bv[q].w, acc[r][q]);
                    }
            }
#pragma unroll
            for (int r = 0; r < 4; ++r)
#pragma unroll
                for (int q = 0; q < 4; ++q) {
                    float s = acc[r][q];
                    if (ADDC && (i0+r == j0+q)) s += c;
                    A[(i0+r)*S + (j0+q)] = s;
                    A[(j0+q)*S + (i0+r)] = s;
                }
        }
    }
    __syncthreads();

    // ---- sweep inverse (register rows) + overlapped Y reload ----
    const int SWT = SWP ? 32 : 64;    // threads participating in sweep barriers
    if (tid < SWT) {
        float a[S];
        if (tid < M) {
#pragma unroll
            for (int g = 0; g < S/4; ++g) {
                float4 v = ((const float4*)(A + tid*S))[g];
                a[4*g+0]=v.x; a[4*g+1]=v.y; a[4*g+2]=v.z; a[4*g+3]=v.w;
            }
        }
#pragma unroll 1
        for (int k = 0; k < M; ++k) {
            if (tid == k) {
#pragma unroll
                for (int g = 0; g < S/4; ++g)
                    ((float4*)rowk)[g] = make_float4(a[4*g],a[4*g+1],a[4*g+2],a[4*g+3]);
            }
            if (SWP) __syncwarp(); else asm volatile("bar.sync 1, 64;" ::: "memory");
            if (tid < M) {
                float d = rowk[k];
                float pinv = 1.0f / d;
                if (tid == k) {
#pragma unroll
                    for (int j = 0; j < S; ++j)
                        a[j] = (j == k) ? -pinv : rowk[j]*pinv;
                } else {
                    float f = rowk[tid] * pinv;
#pragma unroll
                    for (int g = 0; g < S/4; ++g) {
                        float4 r = ((const float4*)rowk)[g];
                        a[4*g+0] = (4*g+0==k) ? f : fmaf(-f, r.x, a[4*g+0]);
                        a[4*g+1] = (4*g+1==k) ? f : fmaf(-f, r.y, a[4*g+1]);
                        a[4*g+2] = (4*g+2==k) ? f : fmaf(-f, r.z, a[4*g+2]);
                        a[4*g+3] = (4*g+3==k) ? f : fmaf(-f, r.w, a[4*g+3]);
                    }
                }
            }
            if (SWP) __syncwarp(); else asm volatile("bar.sync 1, 64;" ::: "memory");
        }
        // theta = I + c*a; write row + weight
        if (tid < M) {
            float sum = 0.f;
#pragma unroll
            for (int j = 0; j < S; ++j) {
                float th = fmaf(c, a[j], (j == tid) ? 1.f : 0.f);
                A[tid*S + j] = th;
                sum = fmaf(th, th, sum);
            }
            wrow[tid] = 1.f / sum;
        }
    } else if (RELOAD) {
        // warps outside the sweep reload Y into Gs concurrently
        for (int t = tid - SWT; t < AROWS*PPAD; t += (NT - SWT)) {
            int k = t / PPAD, col = t % PPAD;
            float v = 0.f;
            if (col < PP && k < M) {
                int f = fidx[k]; int r = f / PG, cc = f % PG;
                v = g_pad_y[(r + col/7)*HP + (cc + col%7)];
            }
            Gs[t] = v;
        }
    }
    __syncthreads();

    // ---- apply: Xh = theta*Y (theta symmetric: read A[j*S+k]) + scatter ----
    if (tid < KT*7) {
        int kt = tid % KT, gt = tid / KT;
        int k0 = 2*kt, k1 = k0 + 1;
        int cbase = gt*8;
        const float4* Yg = (const float4*)Gs + 2*gt;
        float4 s00 = make_float4(0,0,0,0), s01 = s00, s10 = s00, s11 = s00;
#pragma unroll 8
        for (int j = 0; j < M; ++j) {
            float t0 = A[j*S + k0];
            float t1 = A[j*S + k1];
            float4 y0 = Yg[j*NCH4];
            float4 y1 = Yg[j*NCH4 + 1];
            s00.x = fmaf(t0,y0.x,s00.x); s00.y = fmaf(t0,y0.y,s00.y);
            s00.z = fmaf(t0,y0.z,s00.z); s00.w = fmaf(t0,y0.w,s00.w);
            s01.x = fmaf(t0,y1.x,s01.x); s01.y = fmaf(t0,y1.y,s01.y);
            s01.z = fmaf(t0,y1.z,s01.z); s01.w = fmaf(t0,y1.w,s01.w);
            s10.x = fmaf(t1,y0.x,s10.x); s10.y = fmaf(t1,y0.y,s10.y);
            s10.z = fmaf(t1,y0.z,s10.z); s10.w = fmaf(t1,y0.w,s10.w);
            s11.x = fmaf(t1,y1.x,s11.x); s11.y = fmaf(t1,y1.y,s11.y);
            s11.z = fmaf(t1,y1.z,s11.z); s11.w = fmaf(t1,y1.w,s11.w);
        }
        {
            float w0 = wrow[k0]; int f0 = fidx[k0];
            const float v0[8] = {s00.x,s00.y,s00.z,s00.w,s01.x,s01.y,s01.z,s01.w};
#pragma unroll
            for (int cc = 0; cc < 8; ++cc) {
                int col = cbase + cc;
                if (col < PP) atomicAdd(&g_xsum[col*LTOT + f0], v0[cc]*w0);
            }
        }
        if (k1 < M) {
            float w1 = wrow[k1]; int f1 = fidx[k1];
            const float v1[8] = {s10.x,s10.y,s10.z,s10.w,s11.x,s11.y,s11.z,s11.w};
#pragma unroll
            for (int cc = 0; cc < 8; ++cc) {
                int col = cbase + cc;
                if (col < PP) atomicAdd(&g_xsum[col*LTOT + f1], v1[cc]*w1);
            }
        }
    }
    if (tid < M)
        atomicAdd(&g_wsum[fidx[tid]], wrow[tid]);
}

// ---------------- fold + normalize + crop ----------------
__global__ void fold_kernel(float* __restrict__ out, int to_den1) {
    int t = blockIdx.x*blockDim.x + threadIdx.x;
    if (t >= IMG*IMG) return;
    int y = t >> 8, x = t & 255;
    float num = 0.f, den = 0.f;
#pragma unroll
    for (int i = 0; i < 7; ++i) {
        int base = (y + RPAD - i)*PG + (x + RPAD);
#pragma unroll
        for (int j = 0; j < 7; ++j) {
            int f = base - j;
            num += g_xsum[(i*7+j)*LTOT + f];
            den += g_wsum[f];
        }
    }
    float v = num / den;
    if (to_den1) g_den1[t] = v; else out[t] = v;
}

// ---------------- launch ----------------
extern "C" void kernel_launch(void* const* d_in, const int* in_sizes, int n_in,
                              void* d_out, int out_size) {
    const float* y   = (const float*)d_in[0];
    const float* sig = (const float*)d_in[1];
    float* out = (float*)d_out;

    const int PADB = (HP*HP + 255)/256;

    // ---- pass 1 (p=7, m=18) ----
    pad_input_kernel<<<PADB, 256>>>(y, 0);
    bm_kernel<M1, false><<<NC, 256>>>();
    zero_kernel<<<2048, 256>>>();
    denoise_kernel<M1, 20, M1, 9, false, false, false, 128><<<NC, 128>>>(sig);
    fold_kernel<<<(IMG*IMG+255)/256, 256>>>(nullptr, 1);

    // ---- pass 2 (p=7, m=55) ----
    pad_input_kernel<<<PADB, 256>>>(y, 1);
    bm_kernel<M2, true><<<NC, 256>>>();
    zero_kernel<<<2048, 256>>>();
    denoise_kernel<M2, 56, 56, 28, true, true, true, 256><<<NC, 256>>>(sig);
    fold_kernel<<<(IMG*IMG+255)/256, 256>>>(out, 0);
}

// round 4
// speedup vs baseline: 1.4536x; 1.4536x over previous
#include <cuda_runtime.h>
#include <math.h>

// ---------------- problem constants ----------------
#define IMG   256
#define PP    49           // patch pixels (7x7)
#define WN    37           // search window
#define NOFF  (WN*WN)      // 1369
#define INC   18           // WN/2
#define RPAD  21           // PATCH/2 + WN/2
#define HP    298          // IMG + 2*RPAD
#define PG    292          // patch-grid size = IMG + WN - 1
#define LTOT  (PG*PG)      // 85264
#define NC    4096         // total centers (64x64)
#define M1    18
#define M2    55
#define CENTER_OFF (INC*WN + INC)   // 684
#define SA    60           // row stride for A and GsT (15 float4, odd/4 -> 4-phase floor)
#define GROWS 52           // GsT rows: 49 + padding for apply wedges

// ---------------- device scratch ----------------
__device__ float g_pad_y[HP*HP];
__device__ float g_pad_x[HP*HP];
__device__ float g_den1[IMG*IMG];
__device__ int   g_idx1[NC*M1];
__device__ int   g_idx2[NC*M2];
__device__ float g_xsum[PP*LTOT];
__device__ float g_wsum[LTOT];

__device__ __forceinline__ int tri_row(int t) {
    int i = (int)((sqrtf(8.0f*(float)t + 1.0f) - 1.0f)*0.5f);
    while ((i+1)*(i+2)/2 <= t) ++i;
    while (i*(i+1)/2 > t) --i;
    return i;
}

// ---------------- reflect pad 256 -> 298 ----------------
__global__ void pad_input_kernel(const float* __restrict__ src, int use_den1) {
    int t = blockIdx.x * blockDim.x + threadIdx.x;
    if (t >= HP*HP) return;
    int y = t / HP - RPAD, x = t % HP - RPAD;
    y = (y < 0) ? -y : ((y > IMG-1) ? 2*(IMG-1) - y : y);
    x = (x < 0) ? -x : ((x > IMG-1) ? 2*(IMG-1) - x : x);
    float v = use_den1 ? g_den1[y*IMG + x] : src[y*IMG + x];
    if (use_den1) g_pad_x[t] = v; else g_pad_y[t] = v;
}

// ---------------- zero accumulators ----------------
__global__ void zero_kernel() {
    const int total = (PP+1)*LTOT;
    for (int t = blockIdx.x*blockDim.x + threadIdx.x; t < total; t += gridDim.x*blockDim.x) {
        if (t < PP*LTOT) g_xsum[t] = 0.f; else g_wsum[t - PP*LTOT] = 0.f;
    }
}

// ---------------- block matching via exact radix select ----------------
// key = (ordered_dist_bits << 16) | offset_index  -> unique 48-bit keys.
// 4-col tiles; consecutive threads -> consecutive ROWS (stride 43 -> bank 11, conflict-free).
template<int M, bool USE_X>
__global__ __launch_bounds__(256) void bm_kernel() {
    __shared__ float win[43*43 + 16];   // +pad: col-tile reads overrun by <=3
    __shared__ unsigned int hist[256];
    __shared__ unsigned int wsum[8];
    __shared__ unsigned int s_selbin, s_need, s_cnt;

    const float* pad = USE_X ? g_pad_x : g_pad_y;
    int* idx_out = (M == M1) ? g_idx1 : g_idx2;

    const int tid = threadIdx.x;
    const int ci = blockIdx.x >> 6, cj = blockIdx.x & 63;
    const int r0 = 4*ci, c0 = 4*cj;

    for (int t = tid; t < 43*43; t += 256)
        win[t] = pad[(r0 + t/43)*HP + (c0 + t%43)];
    __syncthreads();

    float cp[PP];
#pragma unroll
    for (int d = 0; d < PP; ++d) cp[d] = win[(INC + d/7)*43 + (INC + d%7)];

    unsigned long long key[8];
#pragma unroll
    for (int q = 0; q < 8; ++q) key[q] = ~0ull;

    // 370 tiles = 37 rows x 10 col-groups; u%37 = row (consecutive per lane)
#pragma unroll
    for (int rq = 0; rq < 2; ++rq) {
        int u = tid + 256*rq;
        if (u < 370) {
            int o0 = u % 37;
            int c4 = (u / 37) * 4;
            float s0=0.f, s1=0.f, s2=0.f, s3=0.f;
#pragma unroll
            for (int di = 0; di < 7; ++di) {
                float w[10];
                const float* wr = &win[(o0+di)*43 + c4];
#pragma unroll
                for (int x = 0; x < 10; ++x) w[x] = wr[x];
#pragma unroll
                for (int dj = 0; dj < 7; ++dj) {
                    float cv = cp[di*7+dj];
                    float d0 = w[dj]   - cv; s0 = fmaf(d0,d0,s0);
                    float d1 = w[dj+1] - cv; s1 = fmaf(d1,d1,s1);
                    float d2 = w[dj+2] - cv; s2 = fmaf(d2,d2,s2);
                    float d3 = w[dj+3] - cv; s3 = fmaf(d3,d3,s3);
                }
            }
            float sv[4] = {s0,s1,s2,s3};
#pragma unroll
            for (int cc = 0; cc < 4; ++cc) {
                int o1 = c4 + cc;
                if (o1 < WN) {
                    int t = o0*WN + o1;
                    unsigned int u32 = __float_as_uint(sv[cc]) | 0x80000000u;
                    if (t == CENTER_OFF) u32 = 0u;
                    key[rq*4+cc] = ((unsigned long long)u32 << 16) | (unsigned int)t;
                }
            }
        }
    }

    // 6-pass MSB radix select for the M-th smallest key
    unsigned long long prefix = 0ull;
    unsigned int need = M;
#pragma unroll 1
    for (int pass = 0; pass < 6; ++pass) {
        int shift = 40 - 8*pass;
        hist[tid] = 0;
        __syncthreads();
#pragma unroll
        for (int q = 0; q < 8; ++q) {
            if (key[q] != ~0ull && (key[q] >> (shift + 8)) == prefix)
                atomicAdd(&hist[(unsigned int)(key[q] >> shift) & 255u], 1u);
        }
        __syncthreads();
        unsigned int h = hist[tid];
        unsigned int v = h;
#pragma unroll
        for (int o = 1; o < 32; o <<= 1) {
            unsigned int n = __shfl_up_sync(0xffffffffu, v, o);
            if ((tid & 31) >= o) v += n;
        }
        if ((tid & 31) == 31) wsum[tid >> 5] = v;
        __syncthreads();
        if (tid < 8) {
            unsigned int w = wsum[tid];
            unsigned int x = w;
#pragma unroll
            for (int o = 1; o < 8; o <<= 1) {
                unsigned int n = __shfl_up_sync(0xffu, x, o);
                if (tid >= o) x += n;
            }
            wsum[tid] = x - w;   // exclusive
        }
        __syncthreads();
        unsigned int excl = v - h + wsum[tid >> 5];
        if (excl < need && need <= excl + h) {
            s_selbin = (unsigned int)tid;
            s_need   = need - excl;
        }
        __syncthreads();
        prefix = (prefix << 8) | (unsigned long long)s_selbin;
        need = s_need;
    }
    if (tid == 0) s_cnt = 0;
    __syncthreads();
#pragma unroll
    for (int q = 0; q < 8; ++q) {
        if (key[q] <= prefix) {
            unsigned int pos = atomicAdd(&s_cnt, 1u);
            int t = (int)(key[q] & 0xffffu);
            idx_out[blockIdx.x*M + pos] = (r0 + t/WN)*PG + (c0 + t%WN);
        }
    }
}

// ---------------- batched denoise: one block per group ----------------
// Transposed patch storage GsT[pixel*SA + patch]. A = G G^T (+cI).
// Triangle-register sweep (all threads) -> a = -A^{-1}. theta = I + c*a.
// Xh = theta*Y; wts_k = 1/||theta_k||^2; scatter.
template<int M, int AR, int E, int NCHUNK, int KSH, bool ADDC, bool GUIDE_X, bool RELOAD, int NT>
__global__ __launch_bounds__(NT) void denoise_kernel(const float* __restrict__ sigma_p) {
    __shared__ __align__(16) float GsT[GROWS*SA];
    __shared__ __align__(16) float A[AR*SA];
    __shared__ float rowbuf[2][64];
    __shared__ float wrow[64];
    __shared__ int   fidx[M2];

    const int tid = threadIdx.x;
    const int* idx = (M == M1) ? g_idx1 : g_idx2;
    const float* gpad = GUIDE_X ? g_pad_x : g_pad_y;
    const float sg = *sigma_p;
    const float c  = (float)PP * sg * sg;
    constexpr int T = M*(M+1)/2;

    if (tid < M) fidx[tid] = idx[blockIdx.x*M + tid];
    for (int t = tid; t < AR*SA + GROWS*SA; t += NT) {
        if (t < AR*SA) A[t] = 0.f; else GsT[t - AR*SA] = 0.f;
    }
    __syncthreads();

    // gather guide patches -> GsT[c*SA + k]
    for (int t = tid; t < M*PP; t += NT) {
        int k = t / PP, cc = t % PP;
        int f = fidx[k]; int r = f / PG, q = f % PG;
        GsT[cc*SA + k] = gpad[(r + cc/7)*HP + (q + cc%7)];
    }
    __syncthreads();

    // ---- Gram: A = G G^T (+cI) ----
    if (M == M1) {
        for (int t = tid; t < T; t += NT) {
            int a0 = tri_row(t);
            int b0 = t - a0*(a0+1)/2;
            float s = 0.f;
#pragma unroll 7
            for (int cc = 0; cc < PP; ++cc)
                s = fmaf(GsT[cc*SA + a0], GsT[cc*SA + b0], s);
            if (ADDC && a0 == b0) s += c;
            A[a0*SA + b0] = s;
            A[b0*SA + a0] = s;
        }
    } else {
        // 4x4 register tiles over 14x14 triangle grid (105 tiles)
        if (tid < 105) {
            int ti = tri_row(tid);
            int tj = tid - ti*(ti+1)/2;
            int i0 = 4*ti, j0 = 4*tj;
            float acc[4][4];
#pragma unroll
            for (int r = 0; r < 4; ++r)
#pragma unroll
                for (int q = 0; q < 4; ++q) acc[r][q] = 0.f;
#pragma unroll 7
            for (int cc = 0; cc < PP; ++cc) {
                float4 av = *(const float4*)&GsT[cc*SA + i0];
                float4 bv = *(const float4*)&GsT[cc*SA + j0];
                acc[0][0]=fmaf(av.x,bv.x,acc[0][0]); acc[0][1]=fmaf(av.x,bv.y,acc[0][1]);
                acc[0][2]=fmaf(av.x,bv.z,acc[0][2]); acc[0][3]=fmaf(av.x,bv.w,acc[0][3]);
                acc[1][0]=fmaf(av.y,bv.x,acc[1][0]); acc[1][1]=fmaf(av.y,bv.y,acc[1][1]);
                acc[1][2]=fmaf(av.y,bv.z,acc[1][2]); acc[1][3]=fmaf(av.y,bv.w,acc[1][3]);
                acc[2][0]=fmaf(av.z,bv.x,acc[2][0]); acc[2][1]=fmaf(av.z,bv.y,acc[2][1]);
                acc[2][2]=fmaf(av.z,bv.z,acc[2][2]); acc[2][3]=fmaf(av.z,bv.w,acc[2][3]);
                acc[3][0]=fmaf(av.w,bv.x,acc[3][0]); acc[3][1]=fmaf(av.w,bv.y,acc[3][1]);
                acc[3][2]=fmaf(av.w,bv.z,acc[3][2]); acc[3][3]=fmaf(av.w,bv.w,acc[3][3]);
            }
#pragma unroll
            for (int r = 0; r < 4; ++r)
#pragma unroll
                for (int q = 0; q < 4; ++q) {
                    float s = acc[r][q];
                    if (ADDC && (i0+r == j0+q)) s += c;
                    A[(i0+r)*SA + (j0+q)] = s;
                    A[(j0+q)*SA + (i0+r)] = s;
                }
        }
    }
    __syncthreads();

    // ---- load triangle elements into registers ----
    int ei[E], ej[E]; float ea[E];
#pragma unroll
    for (int e = 0; e < E; ++e) {
        int t = tid + e*NT;
        if (t < T) {
            int i = tri_row(t);
            int j = t - i*(i+1)/2;
            ei[e] = i; ej[e] = j; ea[e] = A[i*SA + j];
        } else { ei[e] = -1; ej[e] = 0; ea[e] = 0.f; }
    }

    // overlapped: reload Y into GsT (Gram done; sweep doesn't touch GsT)
    if (RELOAD) {
        for (int t = tid; t < M*PP; t += NT) {
            int k = t / PP, cc = t % PP;
            int f = fidx[k]; int r = f / PG, q = f % PG;
            GsT[cc*SA + k] = g_pad_y[(r + cc/7)*HP + (q + cc%7)];
        }
    }

    // publish row 0
#pragma unroll
    for (int e = 0; e < E; ++e)
        if (ei[e] >= 0 && (ei[e] == 0 || ej[e] == 0)) rowbuf[0][ei[e] + ej[e]] = ea[e];
    __syncthreads();

    // ---- sweep: 1 barrier per iteration, A resident in registers ----
#pragma unroll 1
    for (int k = 0; k < M; ++k) {
        const float* rk = rowbuf[k & 1];
        float* rn = rowbuf[(k + 1) & 1];
        float pinv = 1.0f / rk[k];
#pragma unroll
        for (int e = 0; e < E; ++e) {
            if (ei[e] >= 0) {
                int i = ei[e], j = ej[e];
                float ri = rk[i], rj = rk[j];
                float v;
                if (i == k)       v = (j == k) ? -pinv : rj * pinv;
                else if (j == k)  v = ri * pinv;
                else              v = fmaf(-ri*pinv, rj, ea[e]);
                ea[e] = v;
                if (i == k+1 || j == k+1) rn[i + j - (k+1)] = v;
            }
        }
        __syncthreads();
    }

    // ---- theta = I + c*a : write both halves ----
#pragma unroll
    for (int e = 0; e < E; ++e) {
        if (ei[e] >= 0) {
            float th = fmaf(c, ea[e], (ei[e] == ej[e]) ? 1.f : 0.f);
            A[ei[e]*SA + ej[e]] = th;
            A[ej[e]*SA + ei[e]] = th;
        }
    }
    __syncthreads();

    // weights: 1/||theta_k||^2
    if (tid < M) {
        float s = 0.f;
#pragma unroll
        for (int g = 0; g < NCHUNK; ++g) {
            float4 v = *(const float4*)&A[tid*SA + 4*g];
            s = fmaf(v.x,v.x, fmaf(v.y,v.y, fmaf(v.z,v.z, fmaf(v.w,v.w, s))));
        }
        wrow[tid] = 1.f / s;
    }
    __syncthreads();

    // ---- apply: Xh[k][c] = theta_k . Y[:,c]; scatter Xh*w and w ----
    {
        int kslot = tid & ((1 << KSH) - 1);
        int wedge = tid >> KSH;           // 4 wedges x 13 pixel columns
        if (kslot < M) {
            float acc[13];
#pragma unroll
            for (int q = 0; q < 13; ++q) acc[q] = 0.f;
#pragma unroll
            for (int g = 0; g < NCHUNK; ++g) {
                float4 th4 = *(const float4*)&A[kslot*SA + 4*g];
                const float* yb = &GsT[(wedge*13)*SA + 4*g];
#pragma unroll
                for (int q = 0; q < 13; ++q) {
                    float4 y4 = *(const float4*)&yb[q*SA];
                    acc[q] = fmaf(th4.x, y4.x, acc[q]);
                    acc[q] = fmaf(th4.y, y4.y, acc[q]);
                    acc[q] = fmaf(th4.z, y4.z, acc[q]);
                    acc[q] = fmaf(th4.w, y4.w, acc[q]);
                }
            }
            float w = wrow[kslot]; int f = fidx[kslot];
#pragma unroll
            for (int q = 0; q < 13; ++q) {
                int cc = wedge*13 + q;
                if (cc < PP) atomicAdd(&g_xsum[cc*LTOT + f], acc[q]*w);
            }
        }
    }
    if (tid < M)
        atomicAdd(&g_wsum[fidx[tid]], wrow[tid]);
}

// ---------------- fold + normalize + crop ----------------
__global__ void fold_kernel(float* __restrict__ out, int to_den1) {
    int t = blockIdx.x*blockDim.x + threadIdx.x;
    if (t >= IMG*IMG) return;
    int y = t >> 8, x = t & 255;
    float num = 0.f, den = 0.f;
#pragma unroll
    for (int i = 0; i < 7; ++i) {
        int base = (y + RPAD - i)*PG + (x + RPAD);
#pragma unroll
        for (int j = 0; j < 7; ++j) {
            int f = base - j;
            num += g_xsum[(i*7+j)*LTOT + f];
            den += g_wsum[f];
        }
    }
    float v = num / den;
    if (to_den1) g_den1[t] = v; else out[t] = v;
}

// ---------------- launch ----------------
extern "C" void kernel_launch(void* const* d_in, const int* in_sizes, int n_in,
                              void* d_out, int out_size) {
    const float* y   = (const float*)d_in[0];
    const float* sig = (const float*)d_in[1];
    float* out = (float*)d_out;

    const int PADB = (HP*HP + 255)/256;

    // ---- pass 1 (p=7, m=18) ----
    pad_input_kernel<<<PADB, 256>>>(y, 0);
    bm_kernel<M1, false><<<NC, 256>>>();
    zero_kernel<<<2048, 256>>>();
    denoise_kernel<M1, 20, 2, 5, 5, false, false, false, 128><<<NC, 128>>>(sig);
    fold_kernel<<<(IMG*IMG+255)/256, 256>>>(nullptr, 1);

    // ---- pass 2 (p=7, m=55) ----
    pad_input_kernel<<<PADB, 256>>>(y, 1);
    bm_kernel<M2, true><<<NC, 256>>>();
    zero_kernel<<<2048, 256>>>();
    denoise_kernel<M2, 56, 7, 14, 6, true, true, true, 256><<<NC, 256>>>(sig);
    fold_kernel<<<(IMG*IMG+255)/256, 256>>>(out, 0);
}